// round 15
// baseline (speedup 1.0000x reference)
#include <cuda_runtime.h>
#include <cuda_fp16.h>
#include <stdint.h>
#include <math.h>

#define BS 4
#define NN 2048
#define H 2
#define F_IN 768
#define F_OUT 768
#define WPR 64
#define BHN (BS * H * NN)
#define NTILE (F_OUT / 128)   // 6 column tiles -> dot partial slots

// ----------------------------- device scratch ------------------------------
__device__ unsigned g_h16[BS * NN * F_IN / 2];          // f16x2 pairs along k
__device__ unsigned g_wT[H * F_OUT * F_IN / 2];         // [hd][n][kpair] f16
__device__ unsigned g_hpT[BS * H * F_OUT * NN / 2];     // [bh][n][jpair] f16
__device__ float g_psp[NTILE * BHN], g_pdp[NTILE * BHN];
__device__ float g_E[BHN], g_G[BHN], g_T[BHN];
__device__ float g_F[BHN], g_Hv[BHN];
__device__ float g_Es[BHN], g_Gs[BHN];
__device__ unsigned g_mask[BS * NN * WPR];     // [b][i][w], diag OR'd in
__device__ unsigned g_maskT[BS * WPR * NN];    // [b][w][i]
__device__ int g_is_i32;

// ------------------------------- helpers ------------------------------------
__device__ __forceinline__ unsigned h2pack(float a, float b) {
    __half2 t = __floats2half2_rn(a, b);
    return *(unsigned*)&t;
}
__device__ __forceinline__ void mma_f16(float* d, const unsigned* a, const unsigned* b) {
    asm volatile(
        "mma.sync.aligned.m16n8k16.row.col.f32.f16.f16.f32 "
        "{%0,%1,%2,%3}, {%4,%5,%6,%7}, {%8,%9}, {%0,%1,%2,%3};"
        : "+f"(d[0]), "+f"(d[1]), "+f"(d[2]), "+f"(d[3])
        : "r"(a[0]), "r"(a[1]), "r"(a[2]), "r"(a[3]), "r"(b[0]), "r"(b[1]));
}

// ---- fragment-permuted smem layout, KB = 4 k-blocks (BK=64 f16) ------------
// A plane: 8 mblks x 4 kblks x 32 units x 4 regs = 4096 u32
// B plane: 16 nblks x 4 kblks x 32 units x 2 regs = 4096 u32
__device__ __forceinline__ void scatterA(unsigned* s, int r, int c0, uint4 v) {
    int t = (r & 7) >> 1;
    int X = ((((r >> 4) * 4 + (c0 >> 3)) * 32 + (r & 7) * 4) << 2)
            + ((r >> 3) & 1) + (((c0 >> 2) & 1) << 1);
    s[X + ((0 ^ t) << 2)] = v.x;
    s[X + ((1 ^ t) << 2)] = v.y;
    s[X + ((2 ^ t) << 2)] = v.z;
    s[X + ((3 ^ t) << 2)] = v.w;
}
__device__ __forceinline__ void scatterBT(unsigned* s, int kp0, int n, uint4 v) {
    int nblk = n >> 3;
    int cx = (nblk & 7) * 2;
    int reg = (kp0 >> 2) & 1;
    int base = (nblk * 4 + (kp0 >> 3)) * 32 + (n & 7) * 4;
    s[(((base + 0) ^ cx) << 1) + reg] = v.x;
    s[(((base + 1) ^ cx) << 1) + reg] = v.y;
    s[(((base + 2) ^ cx) << 1) + reg] = v.z;
    s[(((base + 3) ^ cx) << 1) + reg] = v.w;
}
__device__ __forceinline__ uint4 fragA(const unsigned* s, int mblk, int kk, int lane) {
    int u = ((mblk * 4 + kk) * 32 + lane) ^ (lane >> 3);
    return *(const uint4*)&s[u << 2];
}
__device__ __forceinline__ uint2 fragB(const unsigned* s, int nblk, int kk, int lane) {
    int u = ((nblk * 4 + kk) * 32 + lane) ^ ((nblk & 7) * 2);
    return *(const uint2*)&s[u << 1];
}

// ----------------------- kernel 0a: adjacency dtype -------------------------
__global__ void detect_adj(const unsigned* __restrict__ adj) {
    if (threadIdx.x == 0 && blockIdx.x == 0) {
        int ok = 1;
        for (int i = 0; i < 64; i++)
            if (adj[i] > 1u) ok = 0;
        g_is_i32 = ok;
    }
}

// -------- kernel 0b: fused prep (pack_adj | cvt_h16 | wT transpose) ---------
#define NB_PACK (BS * NN * WPR / 256)            // 2048
#define NB_CVT  (BS * NN * F_IN / 4 / 256)       // 6144
#define NB_WT   ((F_OUT / 32) * (F_IN / 32) * H) // 1152

__global__ __launch_bounds__(256) void prep(const void* __restrict__ adjraw,
                                            const float4* __restrict__ hmat4,
                                            const float* __restrict__ wmat) {
    int blk = blockIdx.x;
    int tid = threadIdx.x;
    if (blk < NB_PACK) {
        int idx = blk * 256 + tid;
        int w = idx % WPR;
        int i = (idx / WPR) % NN;
        int b = idx / (WPR * NN);
        size_t base = (size_t)(idx / WPR) * NN + (size_t)w * 32;
        unsigned bits = 0;
        if (g_is_i32) {
            const uint4* p = (const uint4*)((const unsigned*)adjraw + base);
#pragma unroll
            for (int q = 0; q < 8; q++) {
                uint4 v = p[q];
                bits |= (unsigned)(v.x != 0) << (4 * q);
                bits |= (unsigned)(v.y != 0) << (4 * q + 1);
                bits |= (unsigned)(v.z != 0) << (4 * q + 2);
                bits |= (unsigned)(v.w != 0) << (4 * q + 3);
            }
        } else {
            const unsigned char* p = (const unsigned char*)adjraw + base;
#pragma unroll
            for (int t = 0; t < 32; t++) bits |= (unsigned)(p[t] != 0) << t;
        }
        if ((i >> 5) == w) bits |= 1u << (i & 31);
        g_mask[idx] = bits;
        g_maskT[((size_t)b * WPR + w) * NN + i] = bits;
    } else if (blk < NB_PACK + NB_CVT) {
        int i = (blk - NB_PACK) * 256 + tid;
        float4 v = hmat4[i];
        ((uint2*)g_h16)[i] = make_uint2(h2pack(v.x, v.y), h2pack(v.z, v.w));
    } else {
        __shared__ float t[32][33];
        int li = blk - NB_PACK - NB_CVT;
        int bx = li % (F_OUT / 32);
        int by = (li / (F_OUT / 32)) % (F_IN / 32);
        int z = li / ((F_OUT / 32) * (F_IN / 32));
        int r0 = by * 32, c0 = bx * 32;
        const float* S = wmat + ((size_t)z * F_IN + r0) * F_OUT + c0;
        int cl = tid & 31, rl = tid >> 5;
#pragma unroll
        for (int k = 0; k < 4; k++)
            t[rl + 8 * k][cl] = S[(size_t)(rl + 8 * k) * F_OUT + cl];
        __syncthreads();
        int jj = (tid & 15) * 2, cc = tid >> 4;
#pragma unroll
        for (int k = 0; k < 2; k++) {
            int c = cc + 16 * k;
            size_t e = ((size_t)z * F_OUT + c0 + c) * (F_IN / 2) + (r0 + jj) / 2;
            g_wT[e] = h2pack(t[jj][c], t[jj + 1][c]);
        }
    }
}

// ------------- kernel 1: h_prime GEMM + fused dots + hpT epilogue -----------
#define C_HP (F_IN / 64)   // 12
#define STG 8192           // u32 per stage: A 4096 | B 4096
#define DYN_GEMM 65536     // bytes (2 stages; also covers 128x68 u32 restage)

__global__ __launch_bounds__(256) void hp_gemm_f16(const float* __restrict__ a_src,
                                                   const float* __restrict__ a_dst) {
    extern __shared__ unsigned sm[];
    __shared__ float sred[4][128], sdd[4][128];

    int bh = blockIdx.z, b = bh / H, hd = bh % H;
    int row0 = blockIdx.y * 128, col0 = blockIdx.x * 128;
    const unsigned* A = g_h16 + ((size_t)b * NN + row0) * (F_IN / 2);
    const unsigned* Bm = g_wT + ((size_t)hd * F_OUT + col0) * (F_IN / 2);

    int tid = threadIdx.x, lane = tid & 31, warp = tid >> 5;
    int wm = (warp & 1) * 64, wn = (warp >> 1) * 32;
    int mb0 = wm >> 4, nb0 = wn >> 3;
    int ar = tid >> 1, ac0 = (tid & 1) * 16;
    int bn = tid >> 1, bk0 = (tid & 1) * 16;

    float acc[4][4][4];
#pragma unroll
    for (int mi = 0; mi < 4; mi++)
#pragma unroll
        for (int ni = 0; ni < 4; ni++)
#pragma unroll
            for (int r = 0; r < 4; r++) acc[mi][ni][r] = 0.f;

    uint4 pA[4], pB[4];
#define LOADG(c)                                                          \
    do {                                                                  \
        size_t ga = (size_t)ar * (F_IN / 2) + (c) * 32 + ac0;             \
        size_t gb = (size_t)bn * (F_IN / 2) + (c) * 32 + bk0;             \
        _Pragma("unroll")                                                 \
        for (int q = 0; q < 4; q++) {                                     \
            pA[q] = *(const uint4*)&A[ga + 4 * q];                        \
            pB[q] = *(const uint4*)&Bm[gb + 4 * q];                       \
        }                                                                 \
    } while (0)
#define SCAT(st)                                                          \
    do {                                                                  \
        _Pragma("unroll")                                                 \
        for (int q = 0; q < 4; q++) {                                     \
            scatterA((st), ar, ac0 + 4 * q, pA[q]);                       \
            scatterBT((st) + 4096, bk0 + 4 * q, bn, pB[q]);               \
        }                                                                 \
    } while (0)

    LOADG(0);
    SCAT(sm);
    __syncthreads();

    for (int c = 0; c < C_HP; c++) {
        unsigned* st = sm + (c & 1) * STG;
        if (c + 1 < C_HP) LOADG(c + 1);
#pragma unroll
        for (int kk = 0; kk < 4; kk++) {
            unsigned a_f[4][4], b_f[4][2];
#pragma unroll
            for (int mi = 0; mi < 4; mi++) {
                uint4 v = fragA(st, mb0 + mi, kk, lane);
                a_f[mi][0] = v.x; a_f[mi][1] = v.y; a_f[mi][2] = v.z; a_f[mi][3] = v.w;
            }
#pragma unroll
            for (int ni = 0; ni < 4; ni++) {
                uint2 v = fragB(st + 4096, nb0 + ni, kk, lane);
                b_f[ni][0] = v.x; b_f[ni][1] = v.y;
            }
#pragma unroll
            for (int mi = 0; mi < 4; mi++)
#pragma unroll
                for (int ni = 0; ni < 4; ni++)
                    mma_f16(acc[mi][ni], a_f[mi], b_f[ni]);
        }
        if (c + 1 < C_HP) SCAT(sm + ((c + 1) & 1) * STG);
        __syncthreads();
    }
#undef LOADG
#undef SCAT

    // ---- fused dot partials ----
    const float* sa = a_src + hd * F_OUT;
    const float* da = a_dst + hd * F_OUT;
    float av[4][2], dv[4][2];
#pragma unroll
    for (int ni = 0; ni < 4; ni++)
#pragma unroll
        for (int ch = 0; ch < 2; ch++) {
            int cc = col0 + wn + ni * 8 + 2 * (lane & 3) + ch;
            av[ni][ch] = sa[cc];
            dv[ni][ch] = da[cc];
        }
    int wnid = warp >> 1;
#pragma unroll
    for (int mi = 0; mi < 4; mi++)
#pragma unroll
        for (int rh = 0; rh < 2; rh++) {
            float s = 0.f, d = 0.f;
#pragma unroll
            for (int ni = 0; ni < 4; ni++)
#pragma unroll
                for (int ch = 0; ch < 2; ch++) {
                    float t = tanhf(acc[mi][ni][rh * 2 + ch]);
                    s += t * av[ni][ch];
                    d += t * dv[ni][ch];
                }
            s += __shfl_xor_sync(0xffffffffu, s, 1);
            s += __shfl_xor_sync(0xffffffffu, s, 2);
            d += __shfl_xor_sync(0xffffffffu, d, 1);
            d += __shfl_xor_sync(0xffffffffu, d, 2);
            if ((lane & 3) == 0) {
                int rl = wm + mi * 16 + (lane >> 2) + 8 * rh;
                sred[wnid][rl] = s;
                sdd[wnid][rl] = d;
            }
        }
    __syncthreads();
    if (tid < 128) {
        float s = sred[0][tid] + sred[1][tid] + sred[2][tid] + sred[3][tid];
        float d = sdd[0][tid] + sdd[1][tid] + sdd[2][tid] + sdd[3][tid];
        int row = bh * NN + row0 + tid;
        g_psp[blockIdx.x * BHN + row] = s;
        g_pdp[blockIdx.x * BHN + row] = d;
    }

    // ---- transposed f16 h_prime out: restage via smem ----
    __half* us = (__half*)sm;
#pragma unroll
    for (int mi = 0; mi < 4; mi++)
#pragma unroll
        for (int ni = 0; ni < 4; ni++)
#pragma unroll
            for (int k = 0; k < 4; k++) {
                int rl = wm + mi * 16 + (lane >> 2) + 8 * (k >> 1);
                int cl = wn + ni * 8 + 2 * (lane & 3) + (k & 1);
                us[cl * 136 + rl] = __float2half_rn(acc[mi][ni][k]);
            }
    __syncthreads();
    {
        int n = tid >> 1, seg = tid & 1;
        const uint4* urow = (const uint4*)(sm + n * 68 + seg * 32);
        uint4* dst = (uint4*)(g_hpT + ((size_t)bh * F_OUT + col0 + n) * (NN / 2)
                              + (row0 >> 1) + seg * 32);
#pragma unroll
        for (int q = 0; q < 8; q++) dst[q] = urow[q];
    }
}

// ---------------- kernel 2: exp tables from summed dot partials -------------
__global__ __launch_bounds__(256) void exp_tables() {
    int row = blockIdx.x * blockDim.x + threadIdx.x;
    if (row >= BHN) return;
    float s = 0.f, d = 0.f;
#pragma unroll
    for (int x = 0; x < NTILE; x++) {
        s += g_psp[x * BHN + row];
        d += g_pdp[x * BHN + row];
    }
    g_E[row] = __expf(s);
    g_G[row] = __expf(0.2f * s);
    g_T[row] = __expf(-s);
    g_F[row] = __expf(d);
    g_Hv[row] = __expf(0.2f * d);
}

// -------- kernel 3: row sums of unnormalized attention, scale E/G -----------
__global__ __launch_bounds__(256) void row_stats() {
    int row = blockIdx.x;
    int i = row % NN;
    int bh = row / NN;
    int b = bh / H;
    const unsigned* mrow = g_mask + ((size_t)b * NN + i) * WPR;
    const float* Fv = g_F + (size_t)bh * NN;
    const float* Hv = g_Hv + (size_t)bh * NN;
    float Ei = g_E[row], Gi = g_G[row], Ti = g_T[row];
    int tid = threadIdx.x;
    float sum = 0.f;
    for (int j = tid; j < NN; j += 256) {
        if ((mrow[j >> 5] >> (j & 31)) & 1u) {
            float Fj = Fv[j];
            sum += (Fj >= Ti) ? Ei * Fj : Gi * Hv[j];
        }
    }
    __shared__ float red[8];
    for (int o = 16; o; o >>= 1) sum += __shfl_down_sync(0xffffffffu, sum, o);
    if ((tid & 31) == 0) red[tid >> 5] = sum;
    __syncthreads();
    if (tid == 0) {
        float t0 = 0.f;
        for (int t = 0; t < 8; t++) t0 += red[t];
        float inv = 1.f / t0;
        g_Es[row] = Ei * inv;
        g_Gs[row] = Gi * inv;
    }
}

// ------------- kernel 4: out = P @ h_prime + bias  (in-loop P-gen) ----------
#define C_AT (NN / 64)   // 32

__global__ __launch_bounds__(256) void attn_gemm_f16(float* __restrict__ out,
                                                     const float* __restrict__ bias) {
    extern __shared__ unsigned sm[];
    __shared__ float sT[128], sEs[128], sGs[128];

    int bh = blockIdx.z, b = bh / H;
    int row0 = blockIdx.y * 128, col0 = blockIdx.x * 128;
    const unsigned* Bm = g_hpT + ((size_t)bh * F_OUT + col0) * (NN / 2);
    const float* Fv = g_F + (size_t)bh * NN;
    const float* Hv = g_Hv + (size_t)bh * NN;

    int tid = threadIdx.x, lane = tid & 31, warp = tid >> 5;
    if (tid < 128) {
        int r = bh * NN + row0 + tid;
        sT[tid] = g_T[r];
        sEs[tid] = g_Es[r];
        sGs[tid] = g_Gs[r];
    }
    __syncthreads();

    int wm = (warp & 1) * 64, wn = (warp >> 1) * 32;
    int mb0 = wm >> 4, nb0 = wn >> 3;
    int jl = tid & 15, iblk = tid >> 4;
    int bn = tid >> 1, bk0 = (tid & 1) * 16;

    float acc[4][4][4];
#pragma unroll
    for (int mi = 0; mi < 4; mi++)
#pragma unroll
        for (int ni = 0; ni < 4; ni++)
#pragma unroll
            for (int r = 0; r < 4; r++) acc[mi][ni][r] = 0.f;

    uint4 pB[4];
#define LOADB(c)                                                       \
    do {                                                               \
        size_t gb = (size_t)bn * (NN / 2) + (c) * 32 + bk0;            \
        _Pragma("unroll")                                              \
        for (int q = 0; q < 4; q++) pB[q] = *(const uint4*)&Bm[gb + 4 * q]; \
    } while (0)
// generate 64 j-columns (2 halves of 32) of the P tile in fragment layout
#define GENP(st, c)                                                                 \
    do {                                                                            \
        _Pragma("unroll")                                                           \
        for (int jh = 0; jh < 2; jh++) {                                            \
            int j = (c) * 64 + jh * 32 + 2 * jl;                                    \
            float2 fj = *(const float2*)&Fv[j];                                     \
            float2 hj = *(const float2*)&Hv[j];                                     \
            const unsigned* mT = g_maskT + ((size_t)b * WPR + (j >> 5)) * NN        \
                                 + row0 + iblk * 8;                                 \
            int bitp = 2 * jl;                                                      \
            int jp = jh * 16 + jl;                                                  \
            _Pragma("unroll")                                                       \
            for (int rr = 0; rr < 8; rr++) {                                        \
                int i = iblk * 8 + rr;                                              \
                unsigned m = mT[rr];                                                \
                float p0 = 0.f, p1 = 0.f;                                           \
                if ((m >> bitp) & 1u)                                               \
                    p0 = (fj.x >= sT[i]) ? sEs[i] * fj.x : sGs[i] * hj.x;           \
                if ((m >> (bitp + 1)) & 1u)                                         \
                    p1 = (fj.y >= sT[i]) ? sEs[i] * fj.y : sGs[i] * hj.y;           \
                int tt = (i & 7) >> 1;                                              \
                int X = ((((i >> 4) * 4 + (jp >> 3)) * 32 + (i & 7) * 4) << 2)      \
                        + ((i >> 3) & 1) + (((jp >> 2) & 1) << 1);                  \
                (st)[X + (((jp & 3) ^ tt) << 2)] = h2pack(p0, p1);                  \
            }                                                                       \
        }                                                                           \
    } while (0)

    LOADB(0);
    GENP(sm, 0);
#pragma unroll
    for (int q = 0; q < 4; q++) scatterBT(sm + 4096, bk0 + 4 * q, bn, pB[q]);
    __syncthreads();

    for (int c = 0; c < C_AT; c++) {
        unsigned* st = sm + (c & 1) * STG;
        if (c + 1 < C_AT) LOADB(c + 1);
#pragma unroll
        for (int kk = 0; kk < 4; kk++) {
            unsigned a_f[4][4], b_f[4][2];
#pragma unroll
            for (int mi = 0; mi < 4; mi++) {
                uint4 v = fragA(st, mb0 + mi, kk, lane);
                a_f[mi][0] = v.x; a_f[mi][1] = v.y; a_f[mi][2] = v.z; a_f[mi][3] = v.w;
            }
#pragma unroll
            for (int ni = 0; ni < 4; ni++) {
                uint2 v = fragB(st + 4096, nb0 + ni, kk, lane);
                b_f[ni][0] = v.x; b_f[ni][1] = v.y;
            }
#pragma unroll
            for (int mi = 0; mi < 4; mi++)
#pragma unroll
                for (int ni = 0; ni < 4; ni++)
                    mma_f16(acc[mi][ni], a_f[mi], b_f[ni]);
        }
        if (c + 1 < C_AT) {
            unsigned* st2 = sm + ((c + 1) & 1) * STG;
            GENP(st2, c + 1);
#pragma unroll
            for (int q = 0; q < 4; q++) scatterBT(st2 + 4096, bk0 + 4 * q, bn, pB[q]);
        }
        __syncthreads();
    }
#undef LOADB
#undef GENP

#pragma unroll
    for (int mi = 0; mi < 4; mi++)
#pragma unroll
        for (int ni = 0; ni < 4; ni++) {
            int r = row0 + wm + mi * 16 + (lane >> 2);
            int cc = col0 + wn + ni * 8 + 2 * (lane & 3);
            float b0 = bias[cc], b1 = bias[cc + 1];
            size_t p0 = ((size_t)bh * NN + r) * F_OUT + cc;
            size_t p1 = ((size_t)bh * NN + r + 8) * F_OUT + cc;
            *(float2*)&out[p0] = make_float2(acc[mi][ni][0] + b0, acc[mi][ni][1] + b1);
            *(float2*)&out[p1] = make_float2(acc[mi][ni][2] + b0, acc[mi][ni][3] + b1);
        }
}

// ---------------------------------------------------------------------------
extern "C" void kernel_launch(void* const* d_in, const int* in_sizes, int n_in,
                              void* d_out, int out_size) {
    const float* hmat = 0; const void* adj = 0; const float* wmat = 0;
    const float* a_src = 0; const float* a_dst = 0; const float* bias = 0;
    for (int i = 0; i < n_in; i++) {
        long sz = in_sizes[i];
        if (sz == (long)BS * NN * F_IN)        hmat = (const float*)d_in[i];
        else if (sz == (long)BS * NN * NN)     adj  = d_in[i];
        else if (sz == (long)H * F_IN * F_OUT) wmat = (const float*)d_in[i];
        else if (sz == (long)H * F_OUT) {
            if (!a_src) a_src = (const float*)d_in[i];
            else        a_dst = (const float*)d_in[i];
        }
        else if (sz == (long)F_OUT)            bias = (const float*)d_in[i];
    }
    float* out = (float*)d_out;

    static int attr_done = 0;
    if (!attr_done) {
        cudaFuncSetAttribute(hp_gemm_f16, cudaFuncAttributeMaxDynamicSharedMemorySize,
                             DYN_GEMM);
        cudaFuncSetAttribute(attn_gemm_f16, cudaFuncAttributeMaxDynamicSharedMemorySize,
                             DYN_GEMM);
        attr_done = 1;
    }

    detect_adj<<<1, 32>>>((const unsigned*)adj);
    prep<<<NB_PACK + NB_CVT + NB_WT, 256>>>(adj, (const float4*)hmat, wmat);

    dim3 gGemm(F_OUT / 128, NN / 128, BS * H);  // (6, 16, 8)
    hp_gemm_f16<<<gGemm, 256, DYN_GEMM>>>(a_src, a_dst);
    exp_tables<<<(BHN + 255) / 256, 256>>>();
    row_stats<<<BHN, 256>>>();
    attn_gemm_f16<<<gGemm, 256, DYN_GEMM>>>(out, bias);
}

// round 16
// speedup vs baseline: 1.4070x; 1.4070x over previous
#include <cuda_runtime.h>
#include <cuda_fp16.h>
#include <stdint.h>
#include <math.h>

#define BS 4
#define NN 2048
#define H 2
#define F_IN 768
#define F_OUT 768
#define WPR 64
#define BHN (BS * H * NN)
#define NTILE (F_OUT / 128)   // 6 column tiles -> dot partial slots

// ----------------------------- device scratch ------------------------------
__device__ unsigned g_h16[BS * NN * F_IN / 2];          // f16x2 pairs along k
__device__ unsigned g_wT[H * F_OUT * F_IN / 2];         // [hd][n][kpair] f16
__device__ unsigned g_hpT[BS * H * F_OUT * NN / 2];     // [bh][n][jpair] f16
__device__ float g_psp[NTILE * BHN], g_pdp[NTILE * BHN];
__device__ float g_E[BHN], g_G[BHN], g_T[BHN];
__device__ float g_F[BHN], g_Hv[BHN];
__device__ float g_Es[BHN], g_Gs[BHN];
__device__ unsigned g_mask[BS * NN * WPR];     // [b][i][w], diag OR'd in
__device__ unsigned g_maskT[BS * WPR * NN];    // [b][w][i]
__device__ int g_is_i32;

// ------------------------------- helpers ------------------------------------
__device__ __forceinline__ unsigned h2pack(float a, float b) {
    __half2 t = __floats2half2_rn(a, b);
    return *(unsigned*)&t;
}
__device__ __forceinline__ void mma_f16(float* d, const unsigned* a, const unsigned* b) {
    asm volatile(
        "mma.sync.aligned.m16n8k16.row.col.f32.f16.f16.f32 "
        "{%0,%1,%2,%3}, {%4,%5,%6,%7}, {%8,%9}, {%0,%1,%2,%3};"
        : "+f"(d[0]), "+f"(d[1]), "+f"(d[2]), "+f"(d[3])
        : "r"(a[0]), "r"(a[1]), "r"(a[2]), "r"(a[3]), "r"(b[0]), "r"(b[1]));
}

// ---- fragment-permuted smem layout (u32 = f16 k-pair, BK=32) ---------------
__device__ __forceinline__ void scatterA(unsigned* s, int r, int c0, uint4 v) {
    int t = (r & 7) >> 1;
    int X = ((((r >> 4) * 2 + (c0 >> 3)) * 32 + (r & 7) * 4) << 2)
            + ((r >> 3) & 1) + (((c0 >> 2) & 1) << 1);
    s[X + ((0 ^ t) << 2)] = v.x;
    s[X + ((1 ^ t) << 2)] = v.y;
    s[X + ((2 ^ t) << 2)] = v.z;
    s[X + ((3 ^ t) << 2)] = v.w;
}
__device__ __forceinline__ void scatterBT(unsigned* s, int kp0, int n, uint4 v) {
    int nblk = n >> 3;
    int cx = (nblk & 7) * 2;
    int reg = (kp0 >> 2) & 1;
    int base = (nblk * 2 + (kp0 >> 3)) * 32 + (n & 7) * 4;
    s[(((base + 0) ^ cx) << 1) + reg] = v.x;
    s[(((base + 1) ^ cx) << 1) + reg] = v.y;
    s[(((base + 2) ^ cx) << 1) + reg] = v.z;
    s[(((base + 3) ^ cx) << 1) + reg] = v.w;
}
__device__ __forceinline__ uint4 fragA(const unsigned* s, int mblk, int kk, int lane) {
    int u = ((mblk * 2 + kk) * 32 + lane) ^ (lane >> 3);
    return *(const uint4*)&s[u << 2];
}
__device__ __forceinline__ uint2 fragB(const unsigned* s, int nblk, int kk, int lane) {
    int u = ((nblk * 2 + kk) * 32 + lane) ^ ((nblk & 7) * 2);
    return *(const uint2*)&s[u << 1];
}

// ----------------------- kernel 0a: adjacency dtype -------------------------
__global__ void detect_adj(const unsigned* __restrict__ adj) {
    if (threadIdx.x == 0 && blockIdx.x == 0) {
        int ok = 1;
        for (int i = 0; i < 64; i++)
            if (adj[i] > 1u) ok = 0;
        g_is_i32 = ok;
    }
}

// -------- kernel 0b: fused prep (pack_adj | cvt_h16 | wT transpose) ---------
#define NB_PACK (BS * NN * WPR / 256)            // 2048
#define NB_CVT  (BS * NN * F_IN / 4 / 256)       // 6144
#define NB_WT   ((F_OUT / 32) * (F_IN / 32) * H) // 1152

__global__ __launch_bounds__(256) void prep(const void* __restrict__ adjraw,
                                            const float4* __restrict__ hmat4,
                                            const float* __restrict__ wmat) {
    int blk = blockIdx.x;
    int tid = threadIdx.x;
    if (blk < NB_PACK) {
        int idx = blk * 256 + tid;
        int w = idx % WPR;
        int i = (idx / WPR) % NN;
        int b = idx / (WPR * NN);
        size_t base = (size_t)(idx / WPR) * NN + (size_t)w * 32;
        unsigned bits = 0;
        if (g_is_i32) {
            const uint4* p = (const uint4*)((const unsigned*)adjraw + base);
#pragma unroll
            for (int q = 0; q < 8; q++) {
                uint4 v = p[q];
                bits |= (unsigned)(v.x != 0) << (4 * q);
                bits |= (unsigned)(v.y != 0) << (4 * q + 1);
                bits |= (unsigned)(v.z != 0) << (4 * q + 2);
                bits |= (unsigned)(v.w != 0) << (4 * q + 3);
            }
        } else {
            const unsigned char* p = (const unsigned char*)adjraw + base;
#pragma unroll
            for (int t = 0; t < 32; t++) bits |= (unsigned)(p[t] != 0) << t;
        }
        if ((i >> 5) == w) bits |= 1u << (i & 31);
        g_mask[idx] = bits;
        g_maskT[((size_t)b * WPR + w) * NN + i] = bits;
    } else if (blk < NB_PACK + NB_CVT) {
        int i = (blk - NB_PACK) * 256 + tid;
        float4 v = hmat4[i];
        ((uint2*)g_h16)[i] = make_uint2(h2pack(v.x, v.y), h2pack(v.z, v.w));
    } else {
        __shared__ float t[32][33];
        int li = blk - NB_PACK - NB_CVT;
        int bx = li % (F_OUT / 32);
        int by = (li / (F_OUT / 32)) % (F_IN / 32);
        int z = li / ((F_OUT / 32) * (F_IN / 32));
        int r0 = by * 32, c0 = bx * 32;
        const float* S = wmat + ((size_t)z * F_IN + r0) * F_OUT + c0;
        int cl = tid & 31, rl = tid >> 5;
#pragma unroll
        for (int k = 0; k < 4; k++)
            t[rl + 8 * k][cl] = S[(size_t)(rl + 8 * k) * F_OUT + cl];
        __syncthreads();
        int jj = (tid & 15) * 2, cc = tid >> 4;
#pragma unroll
        for (int k = 0; k < 2; k++) {
            int c = cc + 16 * k;
            size_t e = ((size_t)z * F_OUT + c0 + c) * (F_IN / 2) + (r0 + jj) / 2;
            g_wT[e] = h2pack(t[jj][c], t[jj + 1][c]);
        }
    }
}

// ------------- kernel 1: h_prime GEMM + fused dots + hpT epilogue -----------
#define C_HP (F_IN / 32)   // 24
#define STG_HP 4096        // u32 per stage: A 2048 | B 2048
#define DYN_HP 34816       // bytes

__global__ __launch_bounds__(256, 2) void hp_gemm_f16(const float* __restrict__ a_src,
                                                      const float* __restrict__ a_dst) {
    extern __shared__ unsigned sm[];
    __shared__ float sred[4][128], sdd[4][128];

    int bh = blockIdx.z, b = bh / H, hd = bh % H;
    int row0 = blockIdx.y * 128, col0 = blockIdx.x * 128;
    const unsigned* A = g_h16 + ((size_t)b * NN + row0) * (F_IN / 2);
    const unsigned* Bm = g_wT + ((size_t)hd * F_OUT + col0) * (F_IN / 2);

    int tid = threadIdx.x, lane = tid & 31, warp = tid >> 5;
    int wm = (warp & 1) * 64, wn = (warp >> 1) * 32;
    int mb0 = wm >> 4, nb0 = wn >> 3;
    int ar = tid >> 1, ac = (tid & 1) * 8;
    int bn = tid >> 1, bk = (tid & 1) * 8;

    float acc[4][4][4];
#pragma unroll
    for (int mi = 0; mi < 4; mi++)
#pragma unroll
        for (int ni = 0; ni < 4; ni++)
#pragma unroll
            for (int r = 0; r < 4; r++) acc[mi][ni][r] = 0.f;

    uint4 pA0, pA1, pB0, pB1;
#define LOADG(c)                                                          \
    do {                                                                  \
        size_t ga = (size_t)ar * (F_IN / 2) + (c) * 16 + ac;              \
        pA0 = *(const uint4*)&A[ga]; pA1 = *(const uint4*)&A[ga + 4];     \
        size_t gb = (size_t)bn * (F_IN / 2) + (c) * 16 + bk;              \
        pB0 = *(const uint4*)&Bm[gb]; pB1 = *(const uint4*)&Bm[gb + 4];   \
    } while (0)
#define SCAT(st)                                                          \
    do {                                                                  \
        scatterA((st), ar, ac, pA0); scatterA((st), ar, ac + 4, pA1);     \
        scatterBT((st) + 2048, bk, bn, pB0);                              \
        scatterBT((st) + 2048, bk + 4, bn, pB1);                          \
    } while (0)

    LOADG(0);
    SCAT(sm);
    __syncthreads();

    for (int c = 0; c < C_HP; c++) {
        unsigned* st = sm + (c & 1) * STG_HP;
        if (c + 1 < C_HP) LOADG(c + 1);
#pragma unroll
        for (int kk = 0; kk < 2; kk++) {
            unsigned a_f[4][4], b_f[4][2];
#pragma unroll
            for (int mi = 0; mi < 4; mi++) {
                uint4 v = fragA(st, mb0 + mi, kk, lane);
                a_f[mi][0] = v.x; a_f[mi][1] = v.y; a_f[mi][2] = v.z; a_f[mi][3] = v.w;
            }
#pragma unroll
            for (int ni = 0; ni < 4; ni++) {
                uint2 v = fragB(st + 2048, nb0 + ni, kk, lane);
                b_f[ni][0] = v.x; b_f[ni][1] = v.y;
            }
#pragma unroll
            for (int mi = 0; mi < 4; mi++)
#pragma unroll
                for (int ni = 0; ni < 4; ni++)
                    mma_f16(acc[mi][ni], a_f[mi], b_f[ni]);
        }
        if (c + 1 < C_HP) SCAT(sm + ((c + 1) & 1) * STG_HP);
        __syncthreads();
    }
#undef LOADG
#undef SCAT

    // ---- fused dot partials ----
    const float* sa = a_src + hd * F_OUT;
    const float* da = a_dst + hd * F_OUT;
    float av[4][2], dv[4][2];
#pragma unroll
    for (int ni = 0; ni < 4; ni++)
#pragma unroll
        for (int ch = 0; ch < 2; ch++) {
            int cc = col0 + wn + ni * 8 + 2 * (lane & 3) + ch;
            av[ni][ch] = sa[cc];
            dv[ni][ch] = da[cc];
        }
    int wnid = warp >> 1;
#pragma unroll
    for (int mi = 0; mi < 4; mi++)
#pragma unroll
        for (int rh = 0; rh < 2; rh++) {
            float s = 0.f, d = 0.f;
#pragma unroll
            for (int ni = 0; ni < 4; ni++)
#pragma unroll
                for (int ch = 0; ch < 2; ch++) {
                    float t = tanhf(acc[mi][ni][rh * 2 + ch]);
                    s += t * av[ni][ch];
                    d += t * dv[ni][ch];
                }
            s += __shfl_xor_sync(0xffffffffu, s, 1);
            s += __shfl_xor_sync(0xffffffffu, s, 2);
            d += __shfl_xor_sync(0xffffffffu, d, 1);
            d += __shfl_xor_sync(0xffffffffu, d, 2);
            if ((lane & 3) == 0) {
                int rl = wm + mi * 16 + (lane >> 2) + 8 * rh;
                sred[wnid][rl] = s;
                sdd[wnid][rl] = d;
            }
        }
    __syncthreads();
    if (tid < 128) {
        float s = sred[0][tid] + sred[1][tid] + sred[2][tid] + sred[3][tid];
        float d = sdd[0][tid] + sdd[1][tid] + sdd[2][tid] + sdd[3][tid];
        int row = bh * NN + row0 + tid;
        g_psp[blockIdx.x * BHN + row] = s;
        g_pdp[blockIdx.x * BHN + row] = d;
    }

    // ---- transposed f16 h_prime out: restage via smem ----
    __half* us = (__half*)sm;
#pragma unroll
    for (int mi = 0; mi < 4; mi++)
#pragma unroll
        for (int ni = 0; ni < 4; ni++)
#pragma unroll
            for (int k = 0; k < 4; k++) {
                int rl = wm + mi * 16 + (lane >> 2) + 8 * (k >> 1);
                int cl = wn + ni * 8 + 2 * (lane & 3) + (k & 1);
                us[cl * 136 + rl] = __float2half_rn(acc[mi][ni][k]);
            }
    __syncthreads();
    {
        int n = tid >> 1, seg = tid & 1;
        const uint4* urow = (const uint4*)(sm + n * 68 + seg * 32);
        uint4* dst = (uint4*)(g_hpT + ((size_t)bh * F_OUT + col0 + n) * (NN / 2)
                              + (row0 >> 1) + seg * 32);
#pragma unroll
        for (int q = 0; q < 8; q++) dst[q] = urow[q];
    }
}

// ---------------- kernel 2: exp tables from summed dot partials -------------
__global__ __launch_bounds__(256) void exp_tables() {
    int row = blockIdx.x * blockDim.x + threadIdx.x;
    if (row >= BHN) return;
    float s = 0.f, d = 0.f;
#pragma unroll
    for (int x = 0; x < NTILE; x++) {
        s += g_psp[x * BHN + row];
        d += g_pdp[x * BHN + row];
    }
    g_E[row] = __expf(s);
    g_G[row] = __expf(0.2f * s);
    g_T[row] = __expf(-s);
    g_F[row] = __expf(d);
    g_Hv[row] = __expf(0.2f * d);
}

// -------- kernel 3: row sums of unnormalized attention, scale E/G -----------
__global__ __launch_bounds__(256) void row_stats() {
    int row = blockIdx.x;
    int i = row % NN;
    int bh = row / NN;
    int b = bh / H;
    const unsigned* mrow = g_mask + ((size_t)b * NN + i) * WPR;
    const float* Fv = g_F + (size_t)bh * NN;
    const float* Hv = g_Hv + (size_t)bh * NN;
    float Ei = g_E[row], Gi = g_G[row], Ti = g_T[row];
    int tid = threadIdx.x;
    float sum = 0.f;
    for (int j = tid; j < NN; j += 256) {
        if ((mrow[j >> 5] >> (j & 31)) & 1u) {
            float Fj = Fv[j];
            sum += (Fj >= Ti) ? Ei * Fj : Gi * Hv[j];
        }
    }
    __shared__ float red[8];
    for (int o = 16; o; o >>= 1) sum += __shfl_down_sync(0xffffffffu, sum, o);
    if ((tid & 31) == 0) red[tid >> 5] = sum;
    __syncthreads();
    if (tid == 0) {
        float t0 = 0.f;
        for (int t = 0; t < 8; t++) t0 += red[t];
        float inv = 1.f / t0;
        g_Es[row] = Ei * inv;
        g_Gs[row] = Gi * inv;
    }
}

// ------------- kernel 4: out = P @ h_prime + bias  (in-loop P-gen) ----------
#define C_AT (NN / 32)   // 64
#define STG_AT 4096

__global__ __launch_bounds__(256, 2) void attn_gemm_f16(float* __restrict__ out,
                                                        const float* __restrict__ bias) {
    extern __shared__ unsigned sm[];
    __shared__ float sT[128], sEs[128], sGs[128];

    int bh = blockIdx.z, b = bh / H;
    int row0 = blockIdx.y * 128, col0 = blockIdx.x * 128;
    const unsigned* Bm = g_hpT + ((size_t)bh * F_OUT + col0) * (NN / 2);
    const float* Fv = g_F + (size_t)bh * NN;
    const float* Hv = g_Hv + (size_t)bh * NN;

    int tid = threadIdx.x, lane = tid & 31, warp = tid >> 5;
    if (tid < 128) {
        int r = bh * NN + row0 + tid;
        sT[tid] = g_T[r];
        sEs[tid] = g_Es[r];
        sGs[tid] = g_Gs[r];
    }
    __syncthreads();

    int wm = (warp & 1) * 64, wn = (warp >> 1) * 32;
    int mb0 = wm >> 4, nb0 = wn >> 3;
    int jl = tid & 15, iblk = tid >> 4;
    int bn = tid >> 1, bk = (tid & 1) * 8;

    float acc[4][4][4];
#pragma unroll
    for (int mi = 0; mi < 4; mi++)
#pragma unroll
        for (int ni = 0; ni < 4; ni++)
#pragma unroll
            for (int r = 0; r < 4; r++) acc[mi][ni][r] = 0.f;

    uint4 pB0, pB1;
#define LOADB(c)                                                       \
    do {                                                               \
        size_t gb = (size_t)bn * (NN / 2) + (c) * 16 + bk;             \
        pB0 = *(const uint4*)&Bm[gb]; pB1 = *(const uint4*)&Bm[gb + 4];\
    } while (0)
#define GENP(st, c)                                                                 \
    do {                                                                            \
        int j = (c) * 32 + 2 * jl;                                                  \
        float2 fj = *(const float2*)&Fv[j];                                         \
        float2 hj = *(const float2*)&Hv[j];                                         \
        const unsigned* mT = g_maskT + ((size_t)b * WPR + (j >> 5)) * NN            \
                             + row0 + iblk * 8;                                     \
        int bitp = j & 31;                                                          \
        _Pragma("unroll")                                                           \
        for (int rr = 0; rr < 8; rr++) {                                            \
            int i = iblk * 8 + rr;                                                  \
            unsigned m = mT[rr];                                                    \
            float p0 = 0.f, p1 = 0.f;                                               \
            if ((m >> bitp) & 1u)                                                   \
                p0 = (fj.x >= sT[i]) ? sEs[i] * fj.x : sGs[i] * hj.x;               \
            if ((m >> (bitp + 1)) & 1u)                                             \
                p1 = (fj.y >= sT[i]) ? sEs[i] * fj.y : sGs[i] * hj.y;               \
            int tt = (i & 7) >> 1;                                                  \
            int X = ((((i >> 4) * 2 + (jl >> 3)) * 32 + (i & 7) * 4) << 2)          \
                    + ((i >> 3) & 1) + (((jl >> 2) & 1) << 1);                      \
            (st)[X + (((jl & 3) ^ tt) << 2)] = h2pack(p0, p1);                      \
        }                                                                           \
    } while (0)

    LOADB(0);
    GENP(sm, 0);
    scatterBT(sm + 2048, bk, bn, pB0);
    scatterBT(sm + 2048, bk + 4, bn, pB1);
    __syncthreads();

    for (int c = 0; c < C_AT; c++) {
        unsigned* st = sm + (c & 1) * STG_AT;
        if (c + 1 < C_AT) LOADB(c + 1);
#pragma unroll
        for (int kk = 0; kk < 2; kk++) {
            unsigned a_f[4][4], b_f[4][2];
#pragma unroll
            for (int mi = 0; mi < 4; mi++) {
                uint4 v = fragA(st, mb0 + mi, kk, lane);
                a_f[mi][0] = v.x; a_f[mi][1] = v.y; a_f[mi][2] = v.z; a_f[mi][3] = v.w;
            }
#pragma unroll
            for (int ni = 0; ni < 4; ni++) {
                uint2 v = fragB(st + 2048, nb0 + ni, kk, lane);
                b_f[ni][0] = v.x; b_f[ni][1] = v.y;
            }
#pragma unroll
            for (int mi = 0; mi < 4; mi++)
#pragma unroll
                for (int ni = 0; ni < 4; ni++)
                    mma_f16(acc[mi][ni], a_f[mi], b_f[ni]);
        }
        if (c + 1 < C_AT) {
            unsigned* st2 = sm + ((c + 1) & 1) * STG_AT;
            GENP(st2, c + 1);
            scatterBT(st2 + 2048, bk, bn, pB0);
            scatterBT(st2 + 2048, bk + 4, bn, pB1);
        }
        __syncthreads();
    }
#undef LOADB
#undef GENP

#pragma unroll
    for (int mi = 0; mi < 4; mi++)
#pragma unroll
        for (int ni = 0; ni < 4; ni++) {
            int r = row0 + wm + mi * 16 + (lane >> 2);
            int cc = col0 + wn + ni * 8 + 2 * (lane & 3);
            float b0 = bias[cc], b1 = bias[cc + 1];
            size_t p0 = ((size_t)bh * NN + r) * F_OUT + cc;
            size_t p1 = ((size_t)bh * NN + r + 8) * F_OUT + cc;
            *(float2*)&out[p0] = make_float2(acc[mi][ni][0] + b0, acc[mi][ni][1] + b1);
            *(float2*)&out[p1] = make_float2(acc[mi][ni][2] + b0, acc[mi][ni][3] + b1);
        }
}

// ---------------------------------------------------------------------------
extern "C" void kernel_launch(void* const* d_in, const int* in_sizes, int n_in,
                              void* d_out, int out_size) {
    const float* hmat = 0; const void* adj = 0; const float* wmat = 0;
    const float* a_src = 0; const float* a_dst = 0; const float* bias = 0;
    for (int i = 0; i < n_in; i++) {
        long sz = in_sizes[i];
        if (sz == (long)BS * NN * F_IN)        hmat = (const float*)d_in[i];
        else if (sz == (long)BS * NN * NN)     adj  = d_in[i];
        else if (sz == (long)H * F_IN * F_OUT) wmat = (const float*)d_in[i];
        else if (sz == (long)H * F_OUT) {
            if (!a_src) a_src = (const float*)d_in[i];
            else        a_dst = (const float*)d_in[i];
        }
        else if (sz == (long)F_OUT)            bias = (const float*)d_in[i];
    }
    float* out = (float*)d_out;

    static int attr_done = 0;
    if (!attr_done) {
        cudaFuncSetAttribute(hp_gemm_f16, cudaFuncAttributeMaxDynamicSharedMemorySize,
                             DYN_HP);
        cudaFuncSetAttribute(attn_gemm_f16, cudaFuncAttributeMaxDynamicSharedMemorySize,
                             2 * STG_AT * 4);
        attr_done = 1;
    }

    detect_adj<<<1, 32>>>((const unsigned*)adj);
    prep<<<NB_PACK + NB_CVT + NB_WT, 256>>>(adj, (const float4*)hmat, wmat);

    dim3 gGemm(F_OUT / 128, NN / 128, BS * H);  // (6, 16, 8)
    hp_gemm_f16<<<gGemm, 256, DYN_HP>>>(a_src, a_dst);
    exp_tables<<<(BHN + 255) / 256, 256>>>();
    row_stats<<<BHN, 256>>>();
    attn_gemm_f16<<<gGemm, 256, 2 * STG_AT * 4>>>(out, bias);
}